// round 1
// baseline (speedup 1.0000x reference)
#include <cuda_runtime.h>

#define NUSER 100000
#define NITEM 50000
#define DIN 128

// Scratch (allocation-free rule: __device__ globals)
__device__ float g_Qu[(size_t)NUSER * DIN];
__device__ float g_Ku[(size_t)NUSER * DIN];
__device__ float g_Vu[(size_t)NUSER * DIN];
__device__ float g_Qi[(size_t)NITEM * DIN];
__device__ float g_Ki[(size_t)NITEM * DIN];
__device__ float g_Vi[(size_t)NITEM * DIN];
__device__ float g_du[(size_t)NUSER * 4];
__device__ float g_di[(size_t)NITEM * 4];

// ---------------- packed f32x2 helpers (2x FFMA throughput) ----------------
__device__ __forceinline__ unsigned long long pack_dup(float x) {
    unsigned long long r;
    asm("mov.b64 %0, {%1, %1};" : "=l"(r) : "f"(x));
    return r;
}
__device__ __forceinline__ void fma2(unsigned long long& d, unsigned long long a, unsigned long long b) {
    asm("fma.rn.f32x2 %0, %1, %2, %0;" : "+l"(d) : "l"(a), "l"(b));
}
__device__ __forceinline__ float2 unpack2(unsigned long long v) {
    float2 r;
    asm("mov.b64 {%0, %1}, %2;" : "=f"(r.x), "=f"(r.y) : "l"(v));
    return r;
}

// ---------------- projection GEMM: Y[M,128] = X[M,128] * W[128,128] --------
// W logical col c = h*32+e mapped from weight tensor [H=4][128][32].
// blockIdx.y in {0,1,2} selects which of the 3 weight/output pairs.
// Block: 256 threads, tile 128 rows x 128 cols, 8x8 outputs per thread
// (held as 8x4 f32x2 accumulators).
__global__ __launch_bounds__(256) void proj_kernel(
    const float* __restrict__ X,
    const float* __restrict__ w0, const float* __restrict__ w1, const float* __restrict__ w2,
    float* __restrict__ Y0, float* __restrict__ Y1, float* __restrict__ Y2, int M)
{
    extern __shared__ float sm[];
    float (*Ws)[128] = (float (*)[128])sm;              // 128x128 = 64KB
    float (*As)[128] = (float (*)[128])(sm + 128 * 128); // 8x128   = 4KB

    const float* w = blockIdx.y == 0 ? w0 : (blockIdx.y == 1 ? w1 : w2);
    float* Y       = blockIdx.y == 0 ? Y0 : (blockIdx.y == 1 ? Y1 : Y2);

    const int tid = threadIdx.x;
    // Load W into smem, un-permuting [h][d][e] -> [d][h*32+e]
    #pragma unroll
    for (int i = tid; i < 128 * 128; i += 256) {
        int d = i >> 7, c = i & 127;
        Ws[d][c] = w[(c >> 5) * 4096 + d * 32 + (c & 31)];
    }

    const int ty = tid >> 4, tx = tid & 15;
    const int row0 = blockIdx.x * 128;
    const int lm = tid >> 1;          // row within tile for A staging
    const int lk = (tid & 1) * 4;     // k offset within 8-chunk
    const int lrow = row0 + lm;

    unsigned long long acc[8][4];
    #pragma unroll
    for (int i = 0; i < 8; i++)
        #pragma unroll
        for (int j = 0; j < 4; j++) acc[i][j] = 0ull;

    for (int k0 = 0; k0 < 128; k0 += 8) {
        float4 av = make_float4(0.f, 0.f, 0.f, 0.f);
        if (lrow < M) av = *(const float4*)(X + (size_t)lrow * 128 + k0 + lk);
        __syncthreads();  // previous iter's As reads done (also fences Ws load, iter 0)
        As[lk + 0][lm] = av.x;
        As[lk + 1][lm] = av.y;
        As[lk + 2][lm] = av.z;
        As[lk + 3][lm] = av.w;
        __syncthreads();
        #pragma unroll
        for (int k = 0; k < 8; k++) {
            float a[8];
            *(float4*)(a)     = *(const float4*)&As[k][ty * 8];
            *(float4*)(a + 4) = *(const float4*)&As[k][ty * 8 + 4];
            unsigned long long b2[4];
            const unsigned long long* bp = (const unsigned long long*)&Ws[k0 + k][tx * 8];
            b2[0] = bp[0]; b2[1] = bp[1]; b2[2] = bp[2]; b2[3] = bp[3];
            #pragma unroll
            for (int i = 0; i < 8; i++) {
                unsigned long long pa = pack_dup(a[i]);
                #pragma unroll
                for (int j = 0; j < 4; j++) fma2(acc[i][j], pa, b2[j]);
            }
        }
    }

    #pragma unroll
    for (int i = 0; i < 8; i++) {
        int row = row0 + ty * 8 + i;
        if (row < M) {
            float o[8];
            #pragma unroll
            for (int j = 0; j < 4; j++) {
                float2 t = unpack2(acc[i][j]);
                o[2 * j] = t.x; o[2 * j + 1] = t.y;
            }
            float* yp = Y + (size_t)row * 128 + tx * 8;
            *(float4*)(yp)     = make_float4(o[0], o[1], o[2], o[3]);
            *(float4*)(yp + 4) = make_float4(o[4], o[5], o[6], o[7]);
        }
    }
}

// ---------------- fused edge pass: one warp per edge ------------------------
// lane l handles head h = l>>3, 4 contiguous dims at (l&7)*4.
// w = exp(q.k) per head; accumulate unnormalized numerator into Z and the
// denominator into denom — normalization happens once in finalize.
__global__ __launch_bounds__(256) void edge_kernel(
    const float* __restrict__ Q, const float* __restrict__ K, const float* __restrict__ V,
    const int* __restrict__ srcI, const int* __restrict__ dstI,
    float* __restrict__ Z, float* __restrict__ denom, int nE)
{
    int e = (int)((blockIdx.x * 256 + threadIdx.x) >> 5);
    if (e >= nE) return;
    const int lane = threadIdx.x & 31;
    const int s = __ldg(srcI + e);
    const int d = __ldg(dstI + e);
    const int h = lane >> 3;
    const int off = h * 32 + (lane & 7) * 4;

    const float4 q4 = *(const float4*)(Q + (size_t)d * 128 + off);
    const float4 k4 = *(const float4*)(K + (size_t)s * 128 + off);
    float p = q4.x * k4.x + q4.y * k4.y + q4.z * k4.z + q4.w * k4.w;
    // reduce within each 8-lane head group
    p += __shfl_xor_sync(0xffffffffu, p, 1);
    p += __shfl_xor_sync(0xffffffffu, p, 2);
    p += __shfl_xor_sync(0xffffffffu, p, 4);
    const float wgt = expf(p);

    if ((lane & 7) == 0) atomicAdd(denom + (size_t)d * 4 + h, wgt);

    const float4 v4 = *(const float4*)(V + (size_t)s * 128 + off);
    float* zp = Z + (size_t)d * 128 + off;
    asm volatile("red.global.add.v4.f32 [%0], {%1, %2, %3, %4};"
                 :: "l"(zp), "f"(wgt * v4.x), "f"(wgt * v4.y), "f"(wgt * v4.z), "f"(wgt * v4.w)
                 : "memory");
}

// ---------------- finalize: z = relu(z / denom), 0 for empty segments -------
__global__ __launch_bounds__(256) void finalize_kernel(
    float* __restrict__ Z, const float* __restrict__ denom, int N)
{
    int i = blockIdx.x * 256 + threadIdx.x;  // over N*32 float4s
    if (i >= N * 32) return;
    const int n = i >> 5;
    const int h = (i & 31) >> 3;
    const float sden = denom[(size_t)n * 4 + h];
    const float inv = (sden > 0.f) ? (1.f / sden) : 0.f;
    float4 z = ((const float4*)Z)[i];
    z.x = fmaxf(z.x * inv, 0.f);
    z.y = fmaxf(z.y * inv, 0.f);
    z.z = fmaxf(z.z * inv, 0.f);
    z.w = fmaxf(z.w * inv, 0.f);
    ((float4*)Z)[i] = z;
}

extern "C" void kernel_launch(void* const* d_in, const int* in_sizes, int n_in,
                              void* d_out, int out_size)
{
    const float* h_user    = (const float*)d_in[0];
    const float* h_item    = (const float*)d_in[1];
    const int*   edge_user = (const int*)d_in[2];
    const int*   edge_item = (const int*)d_in[3];
    const float* u_wq = (const float*)d_in[4];
    const float* u_wk = (const float*)d_in[5];
    const float* u_wv = (const float*)d_in[6];
    const float* i_wq = (const float*)d_in[7];
    const float* i_wk = (const float*)d_in[8];
    const float* i_wv = (const float*)d_in[9];
    float* out = (float*)d_out;

    const int nE = in_sizes[2];
    const int Mu = in_sizes[0] / DIN;
    const int Mi = in_sizes[1] / DIN;

    float *Qu, *Ku, *Vu, *Qi, *Ki, *Vi, *du, *di;
    cudaGetSymbolAddress((void**)&Qu, g_Qu);
    cudaGetSymbolAddress((void**)&Ku, g_Ku);
    cudaGetSymbolAddress((void**)&Vu, g_Vu);
    cudaGetSymbolAddress((void**)&Qi, g_Qi);
    cudaGetSymbolAddress((void**)&Ki, g_Ki);
    cudaGetSymbolAddress((void**)&Vi, g_Vi);
    cudaGetSymbolAddress((void**)&du, g_du);
    cudaGetSymbolAddress((void**)&di, g_di);

    const int SMEM_BYTES = (128 * 128 + 8 * 128) * (int)sizeof(float);  // 69632
    cudaFuncSetAttribute(proj_kernel, cudaFuncAttributeMaxDynamicSharedMemorySize, SMEM_BYTES);

    // zero accumulators (d_out is the numerator accumulator; poisoned by harness)
    cudaMemsetAsync(out, 0, (size_t)out_size * sizeof(float));
    cudaMemsetAsync(du, 0, sizeof(float) * (size_t)NUSER * 4);
    cudaMemsetAsync(di, 0, sizeof(float) * (size_t)NITEM * 4);

    // projections: users (Qu,Ku,Vu) and items (Qi,Ki,Vi)
    dim3 gU((Mu + 127) / 128, 3), gI((Mi + 127) / 128, 3);
    proj_kernel<<<gU, 256, SMEM_BYTES>>>(h_user, u_wq, u_wk, u_wv, Qu, Ku, Vu, Mu);
    proj_kernel<<<gI, 256, SMEM_BYTES>>>(h_item, i_wq, i_wk, i_wv, Qi, Ki, Vi, Mi);

    const int eBlocks = (nE + 7) / 8;
    // i2u: dst=user (Q from users), src=item (K,V from items)
    edge_kernel<<<eBlocks, 256>>>(Qu, Ki, Vi, edge_item, edge_user, out, du, nE);
    // u2i: dst=item, src=user
    edge_kernel<<<eBlocks, 256>>>(Qi, Ku, Vu, edge_user, edge_item, out + (size_t)Mu * 128, di, nE);

    finalize_kernel<<<(Mu * 32 + 255) / 256, 256>>>(out, du, Mu);
    finalize_kernel<<<(Mi * 32 + 255) / 256, 256>>>(out + (size_t)Mu * 128, di, Mi);
}

// round 3
// speedup vs baseline: 1.1299x; 1.1299x over previous
#include <cuda_runtime.h>
#include <cuda_bf16.h>
#include <mma.h>
#include <cstdint>

using namespace nvcuda;

#define NUSER 100000
#define NITEM 50000
#define DIN 128

// Scratch (allocation-free rule: __device__ globals)
__device__ float g_Qu[(size_t)NUSER * DIN];
__device__ float g_Ku[(size_t)NUSER * DIN];
__device__ float g_Vu[(size_t)NUSER * DIN];
__device__ float g_Qi[(size_t)NITEM * DIN];
__device__ float g_Ki[(size_t)NITEM * DIN];
__device__ float g_Vi[(size_t)NITEM * DIN];
__device__ float g_du[(size_t)NUSER * 4];
__device__ float g_di[(size_t)NITEM * 4];

// ============ projection GEMM: Y[M,128] = X[M,128] @ Wlogical[128,128] ======
// Wlogical[k][h*32+e] = w[h][k][e].  bf16 wmma with 3-term split emulation:
//   x = hi + lo (bf16),  x*y ~= xh*yh + xl*yh + xh*yl   (fp32 accumulate)
// CTA: 128x128 output tile, K=128 staged fully in smem. 8 warps, 32x64 each.

static constexpr int LDA = 136;   // bf16 elems (272B rows: conflict-free ldmatrix)
static constexpr int LDB = 136;
static constexpr int LDO = 132;   // f32 elems for epilogue bounce
// smem: Ah[128*136], Al, Bh, Bl (bf16) = 4 * 34816 B = 139264 B
static constexpr int SMEM_PROJ = 4 * 128 * LDA * 2;

__global__ __launch_bounds__(256, 1) void proj_wmma(
    const float* __restrict__ X,
    const float* __restrict__ w0, const float* __restrict__ w1, const float* __restrict__ w2,
    float* __restrict__ Y0, float* __restrict__ Y1, float* __restrict__ Y2, int M)
{
    extern __shared__ char smraw[];
    __nv_bfloat16* Ah = (__nv_bfloat16*)smraw;
    __nv_bfloat16* Al = Ah + 128 * LDA;
    __nv_bfloat16* Bh = Al + 128 * LDA;
    __nv_bfloat16* Bl = Bh + 128 * LDB;

    const float* w = blockIdx.y == 0 ? w0 : (blockIdx.y == 1 ? w1 : w2);
    float* Y       = blockIdx.y == 0 ? Y0 : (blockIdx.y == 1 ? Y1 : Y2);

    const int tid  = threadIdx.x;
    const int wid  = tid >> 5;
    const int lane = tid & 31;
    const int tile0 = blockIdx.x * 128;

    // ---- stage W -> Bh/Bl : B[k][n] = Wlogical[k][n] ----
    #pragma unroll 4
    for (int i = tid; i < 128 * 128; i += 256) {
        const int k = i >> 7, n = i & 127;
        const float v = w[(n >> 5) * 4096 + k * 32 + (n & 31)];
        const __nv_bfloat16 hi = __float2bfloat16(v);
        const __nv_bfloat16 lo = __float2bfloat16(v - __bfloat162float(hi));
        Bh[k * LDB + n] = hi;
        Bl[k * LDB + n] = lo;
    }

    // ---- stage X tile -> Ah/Al (warp per row, float4 per lane) ----
    #pragma unroll
    for (int r0 = 0; r0 < 128; r0 += 8) {
        const int row = r0 + wid;
        const int grow = tile0 + row;
        float4 av = make_float4(0.f, 0.f, 0.f, 0.f);
        if (grow < M) av = *(const float4*)(X + (size_t)grow * 128 + lane * 4);
        const float vs[4] = {av.x, av.y, av.z, av.w};
        #pragma unroll
        for (int j = 0; j < 4; j++) {
            const __nv_bfloat16 hi = __float2bfloat16(vs[j]);
            const __nv_bfloat16 lo = __float2bfloat16(vs[j] - __bfloat162float(hi));
            Ah[row * LDA + lane * 4 + j] = hi;
            Al[row * LDA + lane * 4 + j] = lo;
        }
    }
    __syncthreads();

    // ---- compute: warp (wr, wc) owns rows wr*32..+32, cols wc*64..+64 ----
    const int wr = wid >> 1;
    const int wc = wid & 1;

    wmma::fragment<wmma::accumulator, 16, 16, 16, float> c[2][4];
    #pragma unroll
    for (int i = 0; i < 2; i++)
        #pragma unroll
        for (int j = 0; j < 4; j++) wmma::fill_fragment(c[i][j], 0.f);

    #pragma unroll
    for (int t = 0; t < 3; t++) {
        const __nv_bfloat16* Ap = (t == 1) ? Al : Ah;   // hh, lh, hl
        const __nv_bfloat16* Bp = (t == 2) ? Bl : Bh;
        #pragma unroll
        for (int k = 0; k < 128; k += 16) {
            wmma::fragment<wmma::matrix_a, 16, 16, 16, __nv_bfloat16, wmma::row_major> a[2];
            wmma::fragment<wmma::matrix_b, 16, 16, 16, __nv_bfloat16, wmma::row_major> b[4];
            #pragma unroll
            for (int i = 0; i < 2; i++)
                wmma::load_matrix_sync(a[i], Ap + (wr * 32 + i * 16) * LDA + k, LDA);
            #pragma unroll
            for (int j = 0; j < 4; j++)
                wmma::load_matrix_sync(b[j], Bp + k * LDB + wc * 64 + j * 16, LDB);
            #pragma unroll
            for (int i = 0; i < 2; i++)
                #pragma unroll
                for (int j = 0; j < 4; j++)
                    wmma::mma_sync(c[i][j], a[i], b[j], c[i][j]);
        }
    }
    __syncthreads();  // all smem reads done before bounce overwrites

    // ---- epilogue: bounce through smem for coalesced stores ----
    float* Os = (float*)smraw;   // 128 x LDO f32 = 67584 B (fits in staged region)
    #pragma unroll
    for (int i = 0; i < 2; i++)
        #pragma unroll
        for (int j = 0; j < 4; j++)
            wmma::store_matrix_sync(Os + (wr * 32 + i * 16) * LDO + wc * 64 + j * 16,
                                    c[i][j], LDO, wmma::mem_row_major);
    __syncthreads();

    #pragma unroll
    for (int i = 0; i < 16; i++) {
        const int f = i * 256 + tid;        // 4096 float4s = 128 rows x 32
        const int row = f >> 5, c4 = f & 31;
        const int grow = tile0 + row;
        if (grow < M) {
            const float* p = Os + row * LDO + c4 * 4;
            *(float4*)(Y + (size_t)grow * 128 + c4 * 4) =
                make_float4(p[0], p[1], p[2], p[3]);
        }
    }
}

// ---------------- fused edge pass: one warp per edge ------------------------
// lane l: head h = l>>3, 4 dims at (l&7)*4. w = exp(q.k); accumulate
// unnormalized numerator into Z (red.global.v4) and denominator into denom.
__global__ __launch_bounds__(256) void edge_kernel(
    const float* __restrict__ Q, const float* __restrict__ K, const float* __restrict__ V,
    const int* __restrict__ srcI, const int* __restrict__ dstI,
    float* __restrict__ Z, float* __restrict__ denom, int nE)
{
    int e = (int)((blockIdx.x * 256 + threadIdx.x) >> 5);
    if (e >= nE) return;
    const int lane = threadIdx.x & 31;
    const int s = __ldg(srcI + e);
    const int d = __ldg(dstI + e);
    const int h = lane >> 3;
    const int off = h * 32 + (lane & 7) * 4;

    const float4 q4 = *(const float4*)(Q + (size_t)d * 128 + off);
    const float4 k4 = *(const float4*)(K + (size_t)s * 128 + off);
    float p = q4.x * k4.x + q4.y * k4.y + q4.z * k4.z + q4.w * k4.w;
    p += __shfl_xor_sync(0xffffffffu, p, 1);
    p += __shfl_xor_sync(0xffffffffu, p, 2);
    p += __shfl_xor_sync(0xffffffffu, p, 4);
    const float wgt = expf(p);

    if ((lane & 7) == 0) atomicAdd(denom + (size_t)d * 4 + h, wgt);

    const float4 v4 = *(const float4*)(V + (size_t)s * 128 + off);
    float* zp = Z + (size_t)d * 128 + off;
    asm volatile("red.global.add.v4.f32 [%0], {%1, %2, %3, %4};"
                 :: "l"(zp), "f"(wgt * v4.x), "f"(wgt * v4.y), "f"(wgt * v4.z), "f"(wgt * v4.w)
                 : "memory");
}

// ---------------- finalize: z = relu(z / denom) -----------------------------
__global__ __launch_bounds__(256) void finalize_kernel(
    float* __restrict__ Z, const float* __restrict__ denom, int N)
{
    int i = blockIdx.x * 256 + threadIdx.x;
    if (i >= N * 32) return;
    const int n = i >> 5;
    const int h = (i & 31) >> 3;
    const float sden = denom[(size_t)n * 4 + h];
    const float inv = (sden > 0.f) ? (1.f / sden) : 0.f;
    float4 z = ((const float4*)Z)[i];
    z.x = fmaxf(z.x * inv, 0.f);
    z.y = fmaxf(z.y * inv, 0.f);
    z.z = fmaxf(z.z * inv, 0.f);
    z.w = fmaxf(z.w * inv, 0.f);
    ((float4*)Z)[i] = z;
}

extern "C" void kernel_launch(void* const* d_in, const int* in_sizes, int n_in,
                              void* d_out, int out_size)
{
    const float* h_user    = (const float*)d_in[0];
    const float* h_item    = (const float*)d_in[1];
    const int*   edge_user = (const int*)d_in[2];
    const int*   edge_item = (const int*)d_in[3];
    const float* u_wq = (const float*)d_in[4];
    const float* u_wk = (const float*)d_in[5];
    const float* u_wv = (const float*)d_in[6];
    const float* i_wq = (const float*)d_in[7];
    const float* i_wk = (const float*)d_in[8];
    const float* i_wv = (const float*)d_in[9];
    float* out = (float*)d_out;

    const int nE = in_sizes[2];
    const int Mu = in_sizes[0] / DIN;
    const int Mi = in_sizes[1] / DIN;

    float *Qu, *Ku, *Vu, *Qi, *Ki, *Vi, *du, *di;
    cudaGetSymbolAddress((void**)&Qu, g_Qu);
    cudaGetSymbolAddress((void**)&Ku, g_Ku);
    cudaGetSymbolAddress((void**)&Vu, g_Vu);
    cudaGetSymbolAddress((void**)&Qi, g_Qi);
    cudaGetSymbolAddress((void**)&Ki, g_Ki);
    cudaGetSymbolAddress((void**)&Vi, g_Vi);
    cudaGetSymbolAddress((void**)&du, g_du);
    cudaGetSymbolAddress((void**)&di, g_di);

    cudaFuncSetAttribute(proj_wmma, cudaFuncAttributeMaxDynamicSharedMemorySize, SMEM_PROJ);

    cudaMemsetAsync(out, 0, (size_t)out_size * sizeof(float));
    cudaMemsetAsync(du, 0, sizeof(float) * (size_t)NUSER * 4);
    cudaMemsetAsync(di, 0, sizeof(float) * (size_t)NITEM * 4);

    dim3 gU((Mu + 127) / 128, 3), gI((Mi + 127) / 128, 3);
    proj_wmma<<<gU, 256, SMEM_PROJ>>>(h_user, u_wq, u_wk, u_wv, Qu, Ku, Vu, Mu);
    proj_wmma<<<gI, 256, SMEM_PROJ>>>(h_item, i_wq, i_wk, i_wv, Qi, Ki, Vi, Mi);

    const int eBlocks = (nE + 7) / 8;
    edge_kernel<<<eBlocks, 256>>>(Qu, Ki, Vi, edge_item, edge_user, out, du, nE);
    edge_kernel<<<eBlocks, 256>>>(Qi, Ku, Vu, edge_user, edge_item, out + (size_t)Mu * 128, di, nE);

    finalize_kernel<<<(Mu * 32 + 255) / 256, 256>>>(out, du, Mu);
    finalize_kernel<<<(Mi * 32 + 255) / 256, 256>>>(out + (size_t)Mu * 128, di, Mi);
}

// round 4
// speedup vs baseline: 1.2058x; 1.0672x over previous
#include <cuda_runtime.h>
#include <cuda_bf16.h>
#include <mma.h>
#include <cstdint>

using namespace nvcuda;

#define NUSER 100000
#define NITEM 50000
#define DIN 128

// Scratch (allocation-free rule: __device__ globals)
__device__ float g_Qu[(size_t)NUSER * DIN];
__device__ float g_Ku[(size_t)NUSER * DIN];
__device__ float g_Vu[(size_t)NUSER * DIN];
__device__ float g_Qi[(size_t)NITEM * DIN];
__device__ float g_Ki[(size_t)NITEM * DIN];
__device__ float g_Vi[(size_t)NITEM * DIN];
__device__ float g_du[(size_t)NUSER * 4];
__device__ float g_di[(size_t)NITEM * 4];
// pre-split weights: 6 matrices x {hi,lo} planes, logical [k][n] (n = h*32+e)
__device__ __nv_bfloat16 g_WB[6 * 2 * 128 * 128];

// ---------------- W pre-split: fp32 [h][k][e] -> bf16 hi/lo [k][n] ----------
__global__ __launch_bounds__(256) void split_w_kernel(
    const float* __restrict__ w0, const float* __restrict__ w1, const float* __restrict__ w2,
    const float* __restrict__ w3, const float* __restrict__ w4, const float* __restrict__ w5,
    __nv_bfloat16* __restrict__ WB)
{
    const int m = blockIdx.y;
    const float* w = m == 0 ? w0 : m == 1 ? w1 : m == 2 ? w2 : m == 3 ? w3 : m == 4 ? w4 : w5;
    __nv_bfloat16* hi = WB + (size_t)m * 2 * 16384;
    __nv_bfloat16* lo = hi + 16384;
    const int i = blockIdx.x * 256 + threadIdx.x;   // 64 blocks x 256 = 16384
    const int k = i >> 7, n = i & 127;
    const float v = w[(n >> 5) * 4096 + k * 32 + (n & 31)];
    const __nv_bfloat16 h = __float2bfloat16(v);
    hi[i] = h;
    lo[i] = __float2bfloat16(v - __bfloat162float(h));
}

// ============ projection GEMM: Y[M,128] = X[M,128] @ Wlogical[128,128] ======
// bf16 wmma, 3-term split: x*y ~= xh*yh + xl*yh + xh*yl (fp32 accumulate).
// CTA: 64x128 output tile, K=128 fully staged. 8 warps in 2x4, 32x32 each.
// 102KB smem -> 2 CTAs/SM for load/compute overlap across CTAs.

static constexpr int LDA = 136;   // bf16 elems (272B rows)
static constexpr int LDB = 136;
static constexpr int LDO = 132;   // f32 elems for epilogue bounce
static constexpr int SMEM_PROJ = (2 * 64 * LDA + 2 * 128 * LDB) * 2;  // 104448 B

__global__ __launch_bounds__(256, 2) void proj_wmma(
    const float* __restrict__ X,
    const __nv_bfloat16* __restrict__ WB,   // base of this side's 3 matrices
    float* __restrict__ Y0, float* __restrict__ Y1, float* __restrict__ Y2, int M)
{
    extern __shared__ char smraw[];
    __nv_bfloat16* Ah = (__nv_bfloat16*)smraw;          // 64 x LDA
    __nv_bfloat16* Al = Ah + 64 * LDA;
    __nv_bfloat16* Bh = Al + 64 * LDA;                  // 128 x LDB
    __nv_bfloat16* Bl = Bh + 128 * LDB;

    const int mSel = blockIdx.y;                        // 0,1,2 -> q,k,v
    float* Y = mSel == 0 ? Y0 : (mSel == 1 ? Y1 : Y2);
    const __nv_bfloat16* Wm = WB + (size_t)mSel * 2 * 16384;

    const int tid  = threadIdx.x;
    const int wid  = tid >> 5;
    const int lane = tid & 31;
    const int tile0 = blockIdx.x * 64;

    // ---- stage B (both planes) : straight bf16 uint4 copies ----
    {
        const uint4* srcH = (const uint4*)Wm;           // 2048 uint4 per plane
        const uint4* srcL = (const uint4*)(Wm + 16384);
        #pragma unroll
        for (int i = tid; i < 2048; i += 256) {
            const int k = i >> 4, n0 = (i & 15) * 8;
            *(uint4*)&Bh[k * LDB + n0] = srcH[i];
            *(uint4*)&Bl[k * LDB + n0] = srcL[i];
        }
    }

    // ---- stage X tile -> Ah/Al (warp per row, float4 per lane) ----
    #pragma unroll
    for (int r0 = 0; r0 < 64; r0 += 8) {
        const int row = r0 + wid;
        const int grow = tile0 + row;
        float4 av = make_float4(0.f, 0.f, 0.f, 0.f);
        if (grow < M) av = *(const float4*)(X + (size_t)grow * 128 + lane * 4);
        const float vs[4] = {av.x, av.y, av.z, av.w};
        #pragma unroll
        for (int j = 0; j < 4; j++) {
            const __nv_bfloat16 hi = __float2bfloat16(vs[j]);
            Ah[row * LDA + lane * 4 + j] = hi;
            Al[row * LDA + lane * 4 + j] = __float2bfloat16(vs[j] - __bfloat162float(hi));
        }
    }
    __syncthreads();

    // ---- compute: warp (wr, wc) owns rows wr*32..+32, cols wc*32..+32 ----
    const int wr = wid >> 2;
    const int wc = wid & 3;

    wmma::fragment<wmma::accumulator, 16, 16, 16, float> c[2][2];
    #pragma unroll
    for (int i = 0; i < 2; i++)
        #pragma unroll
        for (int j = 0; j < 2; j++) wmma::fill_fragment(c[i][j], 0.f);

    #pragma unroll
    for (int t = 0; t < 3; t++) {
        const __nv_bfloat16* Ap = (t == 1) ? Al : Ah;   // hh, lh, hl
        const __nv_bfloat16* Bp = (t == 2) ? Bl : Bh;
        #pragma unroll
        for (int k = 0; k < 128; k += 16) {
            wmma::fragment<wmma::matrix_a, 16, 16, 16, __nv_bfloat16, wmma::row_major> a[2];
            wmma::fragment<wmma::matrix_b, 16, 16, 16, __nv_bfloat16, wmma::row_major> b[2];
            #pragma unroll
            for (int i = 0; i < 2; i++)
                wmma::load_matrix_sync(a[i], Ap + (wr * 32 + i * 16) * LDA + k, LDA);
            #pragma unroll
            for (int j = 0; j < 2; j++)
                wmma::load_matrix_sync(b[j], Bp + k * LDB + wc * 32 + j * 16, LDB);
            #pragma unroll
            for (int i = 0; i < 2; i++)
                #pragma unroll
                for (int j = 0; j < 2; j++)
                    wmma::mma_sync(c[i][j], a[i], b[j], c[i][j]);
        }
    }
    __syncthreads();  // all smem reads done before bounce overwrites

    // ---- epilogue: bounce through smem for coalesced stores ----
    float* Os = (float*)smraw;   // 64 x LDO f32 = 33792 B (fits in A region)
    #pragma unroll
    for (int i = 0; i < 2; i++)
        #pragma unroll
        for (int j = 0; j < 2; j++)
            wmma::store_matrix_sync(Os + (wr * 32 + i * 16) * LDO + wc * 32 + j * 16,
                                    c[i][j], LDO, wmma::mem_row_major);
    __syncthreads();

    #pragma unroll
    for (int i = 0; i < 8; i++) {
        const int f = i * 256 + tid;        // 2048 float4s = 64 rows x 32
        const int row = f >> 5, c4 = f & 31;
        const int grow = tile0 + row;
        if (grow < M) {
            const float* p = Os + row * LDO + c4 * 4;
            *(float4*)(Y + (size_t)grow * 128 + c4 * 4) =
                make_float4(p[0], p[1], p[2], p[3]);
        }
    }
}

// ---------------- fused edge pass: one warp per edge ------------------------
__global__ __launch_bounds__(256) void edge_kernel(
    const float* __restrict__ Q, const float* __restrict__ K, const float* __restrict__ V,
    const int* __restrict__ srcI, const int* __restrict__ dstI,
    float* __restrict__ Z, float* __restrict__ denom, int nE)
{
    int e = (int)((blockIdx.x * 256 + threadIdx.x) >> 5);
    if (e >= nE) return;
    const int lane = threadIdx.x & 31;
    const int s = __ldg(srcI + e);
    const int d = __ldg(dstI + e);
    const int h = lane >> 3;
    const int off = h * 32 + (lane & 7) * 4;

    const float4 q4 = *(const float4*)(Q + (size_t)d * 128 + off);
    const float4 k4 = *(const float4*)(K + (size_t)s * 128 + off);
    float p = q4.x * k4.x + q4.y * k4.y + q4.z * k4.z + q4.w * k4.w;
    p += __shfl_xor_sync(0xffffffffu, p, 1);
    p += __shfl_xor_sync(0xffffffffu, p, 2);
    p += __shfl_xor_sync(0xffffffffu, p, 4);
    const float wgt = expf(p);

    if ((lane & 7) == 0) atomicAdd(denom + (size_t)d * 4 + h, wgt);

    const float4 v4 = *(const float4*)(V + (size_t)s * 128 + off);
    float* zp = Z + (size_t)d * 128 + off;
    asm volatile("red.global.add.v4.f32 [%0], {%1, %2, %3, %4};"
                 :: "l"(zp), "f"(wgt * v4.x), "f"(wgt * v4.y), "f"(wgt * v4.z), "f"(wgt * v4.w)
                 : "memory");
}

// ---------------- finalize: z = relu(z / denom) -----------------------------
__global__ __launch_bounds__(256) void finalize_kernel(
    float* __restrict__ Z, const float* __restrict__ denom, int N)
{
    int i = blockIdx.x * 256 + threadIdx.x;
    if (i >= N * 32) return;
    const int n = i >> 5;
    const int h = (i & 31) >> 3;
    const float sden = denom[(size_t)n * 4 + h];
    const float inv = (sden > 0.f) ? (1.f / sden) : 0.f;
    float4 z = ((const float4*)Z)[i];
    z.x = fmaxf(z.x * inv, 0.f);
    z.y = fmaxf(z.y * inv, 0.f);
    z.z = fmaxf(z.z * inv, 0.f);
    z.w = fmaxf(z.w * inv, 0.f);
    ((float4*)Z)[i] = z;
}

extern "C" void kernel_launch(void* const* d_in, const int* in_sizes, int n_in,
                              void* d_out, int out_size)
{
    const float* h_user    = (const float*)d_in[0];
    const float* h_item    = (const float*)d_in[1];
    const int*   edge_user = (const int*)d_in[2];
    const int*   edge_item = (const int*)d_in[3];
    const float* u_wq = (const float*)d_in[4];
    const float* u_wk = (const float*)d_in[5];
    const float* u_wv = (const float*)d_in[6];
    const float* i_wq = (const float*)d_in[7];
    const float* i_wk = (const float*)d_in[8];
    const float* i_wv = (const float*)d_in[9];
    float* out = (float*)d_out;

    const int nE = in_sizes[2];
    const int Mu = in_sizes[0] / DIN;
    const int Mi = in_sizes[1] / DIN;

    float *Qu, *Ku, *Vu, *Qi, *Ki, *Vi, *du, *di;
    __nv_bfloat16* WB;
    cudaGetSymbolAddress((void**)&Qu, g_Qu);
    cudaGetSymbolAddress((void**)&Ku, g_Ku);
    cudaGetSymbolAddress((void**)&Vu, g_Vu);
    cudaGetSymbolAddress((void**)&Qi, g_Qi);
    cudaGetSymbolAddress((void**)&Ki, g_Ki);
    cudaGetSymbolAddress((void**)&Vi, g_Vi);
    cudaGetSymbolAddress((void**)&du, g_du);
    cudaGetSymbolAddress((void**)&di, g_di);
    cudaGetSymbolAddress((void**)&WB, g_WB);

    cudaFuncSetAttribute(proj_wmma, cudaFuncAttributeMaxDynamicSharedMemorySize, SMEM_PROJ);

    cudaMemsetAsync(out, 0, (size_t)out_size * sizeof(float));
    cudaMemsetAsync(du, 0, sizeof(float) * (size_t)NUSER * 4);
    cudaMemsetAsync(di, 0, sizeof(float) * (size_t)NITEM * 4);

    // pre-split all 6 weight matrices to bf16 hi/lo
    split_w_kernel<<<dim3(64, 6), 256>>>(u_wq, u_wk, u_wv, i_wq, i_wk, i_wv, WB);

    dim3 gU((Mu + 63) / 64, 3), gI((Mi + 63) / 64, 3);
    proj_wmma<<<gU, 256, SMEM_PROJ>>>(h_user, WB, Qu, Ku, Vu, Mu);
    proj_wmma<<<gI, 256, SMEM_PROJ>>>(h_item, WB + (size_t)3 * 2 * 16384, Qi, Ki, Vi, Mi);

    const int eBlocks = (nE + 7) / 8;
    edge_kernel<<<eBlocks, 256>>>(Qu, Ki, Vi, edge_item, edge_user, out, du, nE);
    edge_kernel<<<eBlocks, 256>>>(Qi, Ku, Vu, edge_user, edge_item, out + (size_t)Mu * 128, di, nE);

    finalize_kernel<<<(Mu * 32 + 255) / 256, 256>>>(out, du, Mu);
    finalize_kernel<<<(Mi * 32 + 255) / 256, 256>>>(out + (size_t)Mu * 128, di, Mi);
}